// round 3
// baseline (speedup 1.0000x reference)
#include <cuda_runtime.h>

#define LAM 0.95f
#define ETA 0.5f
#define B_SZ 128
#define D_SZ 1024
#define VEC_PER_ROW (D_SZ / 4)   // 256
#define ROWS_PER_BLK 8

// out[b,i,j] = LAM*A[b,i,j] + ETA*h[b,i]*h[b,j]
// One block = 8 consecutive rows of one batch. 256 threads; thread t owns
// column-group j4 = t for all 8 rows: hj loaded once, 8 A loads front-batched
// (deep MLP), 8 streaming stores. Streaming hints bypass L2 pollution.
__global__ void __launch_bounds__(256) fastweight_kernel(
    const float4* __restrict__ A,
    const float* __restrict__ h,
    float4* __restrict__ out)
{
    int blk = blockIdx.x;
    int b  = blk >> 7;                    // 128 row-groups per batch (1024/8)
    int rg = blk & 127;
    int i0 = rg * ROWS_PER_BLK;
    int t  = threadIdx.x;                 // j4 in [0,256)

    long long base = ((long long)b * D_SZ + i0) * VEC_PER_ROW + t;

    // hj: L1/L2 resident (512 KB total working set for h)
    const float4 hj = __ldg(((const float4*)h) + b * VEC_PER_ROW + t);

    // hi for the 8 rows (warp-uniform broadcast loads)
    const float* hrow = h + b * D_SZ + i0;
    float hi[ROWS_PER_BLK];
#pragma unroll
    for (int r = 0; r < ROWS_PER_BLK; r++)
        hi[r] = __ldg(hrow + r) * ETA;

    // Front-batch all 8 streaming loads (MLP_p1 = 8)
    float4 a[ROWS_PER_BLK];
#pragma unroll
    for (int r = 0; r < ROWS_PER_BLK; r++)
        a[r] = __ldcs(A + base + (long long)r * VEC_PER_ROW);

#pragma unroll
    for (int r = 0; r < ROWS_PER_BLK; r++) {
        float4 v;
        v.x = fmaf(hi[r], hj.x, a[r].x * LAM);
        v.y = fmaf(hi[r], hj.y, a[r].y * LAM);
        v.z = fmaf(hi[r], hj.z, a[r].z * LAM);
        v.w = fmaf(hi[r], hj.w, a[r].w * LAM);
        __stcs(out + base + (long long)r * VEC_PER_ROW, v);
    }
}

extern "C" void kernel_launch(void* const* d_in, const int* in_sizes, int n_in,
                              void* d_out, int out_size) {
    const float4* A = (const float4*)d_in[0];
    const float*  h = (const float*)d_in[1];
    float4* out = (float4*)d_out;

    // grid = B * (D / ROWS_PER_BLK) = 128 * 128 = 16384 blocks
    int blocks = B_SZ * (D_SZ / ROWS_PER_BLK);
    fastweight_kernel<<<blocks, 256>>>(A, h, out);
}